// round 13
// baseline (speedup 1.0000x reference)
#include <cuda_runtime.h>
#include <math_constants.h>
#include <cstdint>
#include <cstddef>

// Problem shape (fixed by reference)
#define BB  4
#define SS  2048
#define EE  1024
#define HH  64
#define NROWS (BB*SS)     // 8192 query rows
#define CH  256           // keys per split-K chunk (four 64-key subtiles)
#define NCH (SS/CH)       // 8 chunks per batch

// -------- device scratch (no allocations allowed; zero-initialized) --------
__device__ float g_q[NROWS*HH];                  // tf32, e-permuted, pre-scaled
__device__ float g_k[NROWS*HH];                  // tf32, e-permuted
__device__ float g_vt[HH*NROWS];                 // tf32, transposed, tile-permuted
__device__ float g_wp[3*EE*HH];                  // pre-permuted tf32 W (768KB)
__device__ float g_opart[(size_t)NROWS*NCH*HH];  // zero-init matters (combine)
__device__ float g_ml[(size_t)NROWS*NCH*2];      // zero-init matters

// -------- tf32 helpers --------
__device__ __forceinline__ float tf32r(float x) {
    uint32_t u;
    asm("cvt.rna.tf32.f32 %0, %1;" : "=r"(u) : "f"(x));
    return __uint_as_float(u);
}
__device__ __forceinline__ void mma_tf32(float* d, const uint32_t* a, const uint32_t* b) {
    asm volatile(
        "mma.sync.aligned.m16n8k8.row.col.f32.tf32.tf32.f32 "
        "{%0,%1,%2,%3}, {%4,%5,%6,%7}, {%8,%9}, {%0,%1,%2,%3};"
        : "+f"(d[0]), "+f"(d[1]), "+f"(d[2]), "+f"(d[3])
        : "r"(a[0]), "r"(a[1]), "r"(a[2]), "r"(a[3]), "r"(b[0]), "r"(b[1]));
}
__device__ __forceinline__ int perm64(int c) {       // c in 0..63
    return (c & 32) + ((c & 3) << 3) + ((c >> 2) & 7);
}

// ==========================================================================
// Kernel 0: permute W (tf32) into g_wp[mat][k][pn], pn = (n&7)*8 + (n>>3).
// ==========================================================================
__global__ __launch_bounds__(256) void wperm(
    const float* __restrict__ Wq, const float* __restrict__ Wk,
    const float* __restrict__ Wv)
{
    const int mat = blockIdx.y;
    const float* W = (mat == 0) ? Wq : (mat == 1) ? Wk : Wv;
    float* dst = g_wp + mat * (EE*HH);
    #pragma unroll
    for (int i = 0; i < 8; i++) {
        int idx = blockIdx.x * 2048 + i*256 + threadIdx.x;
        int k = idx >> 6, n = idx & 63;
        dst[k*64 + ((n & 7) << 3) + (n >> 3)] = tf32r(W[idx]);
    }
}

// ==========================================================================
// Kernel 1: QKV projection. Block 256 thr (8 warps, one 16-row m-tile each).
// Tile M=128, N=64, BK=32. x natural (conflict-free scalar A-LDS, stride 36);
// W pure copy from g_wp, stride 68. Grid (64, 3) -> ~10 warps/SM.
// Epilogue writes attention-ready layouts.
// ==========================================================================
#define QK_XST 36
#define QK_WST 68

__global__ __launch_bounds__(256) void qkv_proj(
    const float* __restrict__ x,
    const float* __restrict__ bq, const float* __restrict__ bk,
    const float* __restrict__ bv)
{
    __shared__ float xs[128*QK_XST];      // natural [row][k], 18.4 KB
    __shared__ float ws[32*QK_WST];       // permuted [k][pn], 8.7 KB

    const int tid  = threadIdx.x;
    const int warp = tid >> 5;
    const int lane = tid & 31;
    const int g    = lane >> 2;
    const int tig  = lane & 3;
    const int row0 = blockIdx.x * 128;
    const int mat  = blockIdx.y;

    const float* wp   = g_wp + mat * (EE*HH);
    const float* bias = (mat == 0) ? bq : (mat == 1) ? bk : bv;

    // prefetch first tiles: x 128x32 = 1024 f4 (4/thread), W 32x64 = 512 f4 (2/thread)
    float4 xt[4], wt[2];
    #pragma unroll
    for (int i = 0; i < 4; i++) {
        int f4 = i*256 + tid;
        xt[i] = *(const float4*)&x[(size_t)(row0 + (f4>>3))*EE + (f4&7)*4];
    }
    #pragma unroll
    for (int i = 0; i < 2; i++) {
        int f4 = i*256 + tid;
        wt[i] = *(const float4*)&wp[(size_t)(f4>>4)*64 + (f4&15)*4];
    }

    float acc[8][4] = {};

    #pragma unroll 1
    for (int kb = 0; kb < EE; kb += 32) {
        // ---- stage: x natural (tf32), W pure copy ----
        #pragma unroll
        for (int i = 0; i < 4; i++) {
            int f4 = i*256 + tid;
            int r = f4 >> 3, c4 = f4 & 7;
            float4 t;
            t.x = tf32r(xt[i].x); t.y = tf32r(xt[i].y);
            t.z = tf32r(xt[i].z); t.w = tf32r(xt[i].w);
            *(float4*)&xs[r*QK_XST + c4*4] = t;
        }
        #pragma unroll
        for (int i = 0; i < 2; i++) {
            int f4 = i*256 + tid;
            *(float4*)&ws[(f4>>4)*QK_WST + (f4&15)*4] = wt[i];
        }
        __syncthreads();

        if (kb + 32 < EE) {
            #pragma unroll
            for (int i = 0; i < 4; i++) {
                int f4 = i*256 + tid;
                xt[i] = *(const float4*)&x[(size_t)(row0 + (f4>>3))*EE + kb+32 + (f4&7)*4];
            }
            #pragma unroll
            for (int i = 0; i < 2; i++) {
                int f4 = i*256 + tid;
                wt[i] = *(const float4*)&wp[(size_t)(kb+32 + (f4>>4))*64 + (f4&15)*4];
            }
        }

        // ---- compute: warp owns rows warp*16..+15 ----
        #pragma unroll
        for (int ks = 0; ks < 4; ks++) {
            float w1[8], w2[8];
            *(float4*)&w1[0] = *(const float4*)&ws[(8*ks+tig  )*QK_WST + g*8    ];
            *(float4*)&w1[4] = *(const float4*)&ws[(8*ks+tig  )*QK_WST + g*8 + 4];
            *(float4*)&w2[0] = *(const float4*)&ws[(8*ks+tig+4)*QK_WST + g*8    ];
            *(float4*)&w2[4] = *(const float4*)&ws[(8*ks+tig+4)*QK_WST + g*8 + 4];
            const int rb = warp*16 + g;
            uint32_t a[4];
            a[0] = __float_as_uint(xs[ rb   *QK_XST + 8*ks + tig    ]);
            a[1] = __float_as_uint(xs[(rb+8)*QK_XST + 8*ks + tig    ]);
            a[2] = __float_as_uint(xs[ rb   *QK_XST + 8*ks + tig + 4]);
            a[3] = __float_as_uint(xs[(rb+8)*QK_XST + 8*ks + tig + 4]);
            #pragma unroll
            for (int nt = 0; nt < 8; nt++) {
                uint32_t bf[2] = { __float_as_uint(w1[nt]), __float_as_uint(w2[nt]) };
                mma_tf32(acc[nt], a, bf);
            }
        }
        __syncthreads();
    }

    // ---- epilogue: write attention-ready layouts ----
    const int rowa = row0 + warp*16 + g;
    const int rowb = rowa + 8;
    #pragma unroll
    for (int nt = 0; nt < 8; nt++) {
        const int col = nt*8 + 2*tig;
        const float b0 = __ldg(&bias[col]);
        const float b1 = __ldg(&bias[col+1]);
        float v0 = acc[nt][0] + b0, v1 = acc[nt][1] + b1;
        float v2 = acc[nt][2] + b0, v3 = acc[nt][3] + b1;
        if (mat == 0) {            // Q: scale + tf32 + e-permuted
            const int p = perm64(col);
            g_q[(size_t)rowa*HH + p]     = tf32r(v0 * 0.125f);
            g_q[(size_t)rowa*HH + p + 8] = tf32r(v1 * 0.125f);
            g_q[(size_t)rowb*HH + p]     = tf32r(v2 * 0.125f);
            g_q[(size_t)rowb*HH + p + 8] = tf32r(v3 * 0.125f);
        } else if (mat == 1) {     // K: tf32 + e-permuted
            const int p = perm64(col);
            g_k[(size_t)rowa*HH + p]     = tf32r(v0);
            g_k[(size_t)rowa*HH + p + 8] = tf32r(v1);
            g_k[(size_t)rowb*HH + p]     = tf32r(v2);
            g_k[(size_t)rowb*HH + p + 8] = tf32r(v3);
        } else {                   // V: tf32, transposed, key tile-permuted
            const size_t ta = (size_t)(rowa & ~63) + perm64(rowa & 63);
            const size_t tb = (size_t)(rowb & ~63) + perm64(rowb & 63);
            g_vt[(size_t) col   *NROWS + ta] = tf32r(v0);
            g_vt[(size_t)(col+1)*NROWS + ta] = tf32r(v1);
            g_vt[(size_t) col   *NROWS + tb] = tf32r(v2);
            g_vt[(size_t)(col+1)*NROWS + tb] = tf32r(v3);
        }
    }
}

// ==========================================================================
// Kernel 2: split-K causal flash attention (round-12, unchanged).
// ALL staging = pure float4 copy. Block 128 thr; 64 q x 256 keys.
// AST = 68: conflict-free fragment loads. Grid (qt=32, c=8, b=4).
// ==========================================================================
#define AST 68
#define ATTN_SMEM (3*64*AST*4)   // 52.2 KB

__global__ __launch_bounds__(128) void attn_partial()
{
    extern __shared__ float dsm[];
    float* Qs  = dsm;
    float* KPs = dsm + 64*AST;
    float* Vst = dsm + 2*64*AST;

    const int tid  = threadIdx.x;
    const int warp = tid >> 5;
    const int lane = tid & 31;
    const int g    = lane >> 2;
    const int tig  = lane & 3;
    const int qt   = blockIdx.x;
    const int c    = blockIdx.y;
    const int b    = blockIdx.z;
    if (4*c > qt) return;

    const int q0 = qt * 64;
    const int wq = warp * 16;

    // ---- stage Q: pure copy ----
    #pragma unroll
    for (int i = 0; i < 8; i++) {
        int f4 = i*128 + tid;
        int r = f4 >> 4, c4 = f4 & 15;
        *(float4*)&Qs[r*AST + c4*4] =
            *(const float4*)&g_q[((size_t)b*SS + q0 + r)*HH + c4*4];
    }

    float O[8][4] = {};
    float m0 = -CUDART_INF_F, m1 = -CUDART_INF_F;
    float l0 = 0.0f, l1 = 0.0f;

    #pragma unroll 1
    for (int sub = 0; sub < 4; sub++) {
        const int k0 = c*CH + sub*64;
        if (k0 > q0) break;
        const bool diag = (k0 == q0);

        __syncthreads();
        // ---- stage K: pure copy ----
        #pragma unroll
        for (int i = 0; i < 8; i++) {
            int f4 = i*128 + tid;
            int r = f4 >> 4, c4 = f4 & 15;
            *(float4*)&KPs[r*AST + c4*4] =
                *(const float4*)&g_k[((size_t)b*SS + k0 + r)*HH + c4*4];
        }
        // ---- stage V: pure copy from transposed g_vt ----
        #pragma unroll
        for (int i = 0; i < 8; i++) {
            int f4 = i*128 + tid;
            int h = f4 >> 4, j4 = f4 & 15;
            *(float4*)&Vst[h*AST + j4*4] =
                *(const float4*)&g_vt[(size_t)h*NROWS + (size_t)b*SS + k0 + j4*4];
        }
        __syncthreads();

        // ---- Phase A: S = Qhat Khat^T ----
        float S[8][4] = {};
        #pragma unroll
        for (int eb = 0; eb < 2; eb++) {
            float al[8], ah[8];
            *(float4*)&al[0] = *(const float4*)&Qs[(wq+g  )*AST + eb*32 + tig*8    ];
            *(float4*)&al[4] = *(const float4*)&Qs[(wq+g  )*AST + eb*32 + tig*8 + 4];
            *(float4*)&ah[0] = *(const float4*)&Qs[(wq+g+8)*AST + eb*32 + tig*8    ];
            *(float4*)&ah[4] = *(const float4*)&Qs[(wq+g+8)*AST + eb*32 + tig*8 + 4];
            #pragma unroll
            for (int nh = 0; nh < 2; nh++) {
                float kv[4][8];
                #pragma unroll
                for (int j = 0; j < 4; j++) {
                    int nt = nh*4 + j;
                    *(float4*)&kv[j][0] = *(const float4*)&KPs[(nt*8+g)*AST + eb*32 + tig*8    ];
                    *(float4*)&kv[j][4] = *(const float4*)&KPs[(nt*8+g)*AST + eb*32 + tig*8 + 4];
                }
                #pragma unroll
                for (int k2 = 0; k2 < 4; k2++) {
                    uint32_t a[4];
                    a[0] = __float_as_uint(al[2*k2  ]);
                    a[1] = __float_as_uint(ah[2*k2  ]);
                    a[2] = __float_as_uint(al[2*k2+1]);
                    a[3] = __float_as_uint(ah[2*k2+1]);
                    #pragma unroll
                    for (int j = 0; j < 4; j++) {
                        uint32_t bf[2] = { __float_as_uint(kv[j][2*k2]),
                                           __float_as_uint(kv[j][2*k2+1]) };
                        mma_tf32(S[nh*4+j], a, bf);
                    }
                }
            }
        }

        // ---- causal mask (diagonal subtile only) ----
        const int gq0 = q0 + wq + g;
        const int gq1 = gq0 + 8;
        if (diag) {
            #pragma unroll
            for (int nt = 0; nt < 8; nt++) {
                const int kc = k0 + nt*8 + 2*tig;
                if (kc   > gq0) S[nt][0] = -CUDART_INF_F;
                if (kc+1 > gq0) S[nt][1] = -CUDART_INF_F;
                if (kc   > gq1) S[nt][2] = -CUDART_INF_F;
                if (kc+1 > gq1) S[nt][3] = -CUDART_INF_F;
            }
        }

        // ---- online softmax (quad shfl) ----
        float mx0 = -CUDART_INF_F, mx1 = -CUDART_INF_F;
        #pragma unroll
        for (int nt = 0; nt < 8; nt++) {
            mx0 = fmaxf(mx0, fmaxf(S[nt][0], S[nt][1]));
            mx1 = fmaxf(mx1, fmaxf(S[nt][2], S[nt][3]));
        }
        mx0 = fmaxf(mx0, __shfl_xor_sync(0xffffffffu, mx0, 1));
        mx0 = fmaxf(mx0, __shfl_xor_sync(0xffffffffu, mx0, 2));
        mx1 = fmaxf(mx1, __shfl_xor_sync(0xffffffffu, mx1, 1));
        mx1 = fmaxf(mx1, __shfl_xor_sync(0xffffffffu, mx1, 2));

        const float nm0 = fmaxf(m0, mx0), nm1 = fmaxf(m1, mx1);
        const float al0 = __expf(m0 - nm0), al1 = __expf(m1 - nm1);
        m0 = nm0; m1 = nm1;

        float s0 = 0.0f, s1 = 0.0f;
        #pragma unroll
        for (int nt = 0; nt < 8; nt++) {
            S[nt][0] = __expf(S[nt][0] - nm0);
            S[nt][1] = __expf(S[nt][1] - nm0);
            S[nt][2] = __expf(S[nt][2] - nm1);
            S[nt][3] = __expf(S[nt][3] - nm1);
            s0 += S[nt][0] + S[nt][1];
            s1 += S[nt][2] + S[nt][3];
        }
        s0 += __shfl_xor_sync(0xffffffffu, s0, 1);
        s0 += __shfl_xor_sync(0xffffffffu, s0, 2);
        s1 += __shfl_xor_sync(0xffffffffu, s1, 1);
        s1 += __shfl_xor_sync(0xffffffffu, s1, 2);
        l0 = l0*al0 + s0;
        l1 = l1*al1 + s1;
        #pragma unroll
        for (int nt = 0; nt < 8; nt++) {
            O[nt][0] *= al0; O[nt][1] *= al0;
            O[nt][2] *= al1; O[nt][3] *= al1;
        }

        __syncthreads();
        // ---- stage P over K region (tf32, key-permuted) ----
        #pragma unroll
        for (int nt = 0; nt < 8; nt++) {
            const int p0 = perm64(nt*8 + 2*tig);
            KPs[(wq+g  )*AST + p0    ] = tf32r(S[nt][0]);
            KPs[(wq+g  )*AST + p0 + 8] = tf32r(S[nt][1]);
            KPs[(wq+g+8)*AST + p0    ] = tf32r(S[nt][2]);
            KPs[(wq+g+8)*AST + p0 + 8] = tf32r(S[nt][3]);
        }
        __syncthreads();

        // ---- Phase B: O += P V ----
        #pragma unroll
        for (int kb = 0; kb < 2; kb++) {
            float al2[8], ah2[8];
            *(float4*)&al2[0] = *(const float4*)&KPs[(wq+g  )*AST + kb*32 + tig*8    ];
            *(float4*)&al2[4] = *(const float4*)&KPs[(wq+g  )*AST + kb*32 + tig*8 + 4];
            *(float4*)&ah2[0] = *(const float4*)&KPs[(wq+g+8)*AST + kb*32 + tig*8    ];
            *(float4*)&ah2[4] = *(const float4*)&KPs[(wq+g+8)*AST + kb*32 + tig*8 + 4];
            #pragma unroll
            for (int nh = 0; nh < 2; nh++) {
                float vv[4][8];
                #pragma unroll
                for (int j = 0; j < 4; j++) {
                    int nt = nh*4 + j;
                    *(float4*)&vv[j][0] = *(const float4*)&Vst[(nt*8+g)*AST + kb*32 + tig*8    ];
                    *(float4*)&vv[j][4] = *(const float4*)&Vst[(nt*8+g)*AST + kb*32 + tig*8 + 4];
                }
                #pragma unroll
                for (int k2 = 0; k2 < 4; k2++) {
                    uint32_t a[4];
                    a[0] = __float_as_uint(al2[2*k2  ]);
                    a[1] = __float_as_uint(ah2[2*k2  ]);
                    a[2] = __float_as_uint(al2[2*k2+1]);
                    a[3] = __float_as_uint(ah2[2*k2+1]);
                    #pragma unroll
                    for (int j = 0; j < 4; j++) {
                        uint32_t bf[2] = { __float_as_uint(vv[j][2*k2]),
                                           __float_as_uint(vv[j][2*k2+1]) };
                        mma_tf32(O[nh*4+j], a, bf);
                    }
                }
            }
        }
    }

    // ---- write unnormalized partials + (m, l) ----
    const size_t r0 = (size_t)b*SS + q0 + wq + g;
    const size_t r1 = r0 + 8;
    #pragma unroll
    for (int nt = 0; nt < 8; nt++) {
        const int col = nt*8 + 2*tig;
        *(float2*)&g_opart[(r0*NCH + c)*HH + col] = make_float2(O[nt][0], O[nt][1]);
        *(float2*)&g_opart[(r1*NCH + c)*HH + col] = make_float2(O[nt][2], O[nt][3]);
    }
    if (tig == 0) {
        g_ml[(r0*NCH + c)*2 + 0] = m0;
        g_ml[(r0*NCH + c)*2 + 1] = l0;
        g_ml[(r1*NCH + c)*2 + 0] = m1;
        g_ml[(r1*NCH + c)*2 + 1] = l1;
    }
}

// ==========================================================================
// Kernel 3: combine. Fixed fully-unrolled 8-chunk loop (zero-init chunks
// contribute nothing; max over extra zeros only shifts normalization).
// ==========================================================================
__global__ __launch_bounds__(64) void attn_combine(float* __restrict__ out)
{
    const size_t r = blockIdx.x;
    const int    e = threadIdx.x;

    float mc[NCH], lc[NCH], op[NCH];
    #pragma unroll
    for (int c = 0; c < NCH; c++) {
        float2 ml = *(const float2*)&g_ml[(r*NCH + c)*2];
        mc[c] = ml.x; lc[c] = ml.y;
        op[c] = g_opart[(r*NCH + c)*HH + e];
    }
    float M = mc[0];
    #pragma unroll
    for (int c = 1; c < NCH; c++) M = fmaxf(M, mc[c]);

    float L = 0.0f, o = 0.0f;
    #pragma unroll
    for (int c = 0; c < NCH; c++) {
        float w = __expf(mc[c] - M);
        L += lc[c] * w;
        o  = fmaf(w, op[c], o);
    }
    out[r*HH + e] = o / L;
}

// ==========================================================================
extern "C" void kernel_launch(void* const* d_in, const int* in_sizes, int n_in,
                              void* d_out, int out_size)
{
    const float* x  = (const float*)d_in[0];
    const float* Wq = (const float*)d_in[1];
    const float* bq = (const float*)d_in[2];
    const float* Wk = (const float*)d_in[3];
    const float* bk = (const float*)d_in[4];
    const float* Wv = (const float*)d_in[5];
    const float* bv = (const float*)d_in[6];
    float* out = (float*)d_out;

    cudaFuncSetAttribute(attn_partial,
                         cudaFuncAttributeMaxDynamicSharedMemorySize, ATTN_SMEM);

    dim3 gw(32, 3);
    wperm<<<gw, 256>>>(Wq, Wk, Wv);

    dim3 gq(NROWS / 128, 3);
    qkv_proj<<<gq, 256>>>(x, bq, bk, bv);

    dim3 ga(SS / 64, NCH, BB);
    attn_partial<<<ga, 128, ATTN_SMEM>>>();

    attn_combine<<<NROWS, 64>>>(out);
}

// round 14
// speedup vs baseline: 1.0543x; 1.0543x over previous
#include <cuda_runtime.h>
#include <math_constants.h>
#include <cstdint>
#include <cstddef>

// Problem shape (fixed by reference)
#define BB  4
#define SS  2048
#define EE  1024
#define HH  64
#define NROWS (BB*SS)     // 8192 query rows
#define CH  256           // keys per split-K chunk (four 64-key subtiles)
#define NCH (SS/CH)       // 8 chunks per batch

// -------- device scratch (no allocations allowed; zero-initialized) --------
__device__ float g_q[NROWS*HH];                  // tf32, e-permuted, pre-scaled
__device__ float g_k[NROWS*HH];                  // tf32, e-permuted
__device__ float g_vt[HH*NROWS];                 // tf32, transposed, tile-permuted
__device__ float g_wp[3*EE*HH];                  // pre-permuted tf32 W (768KB)
__device__ float g_opart[(size_t)NROWS*NCH*HH];  // zero-init matters (combine)
__device__ float g_ml[(size_t)NROWS*NCH*2];      // zero-init matters

// -------- tf32 helpers --------
__device__ __forceinline__ float tf32r(float x) {
    uint32_t u;
    asm("cvt.rna.tf32.f32 %0, %1;" : "=r"(u) : "f"(x));
    return __uint_as_float(u);
}
__device__ __forceinline__ void mma_tf32(float* d, const uint32_t* a, const uint32_t* b) {
    asm volatile(
        "mma.sync.aligned.m16n8k8.row.col.f32.tf32.tf32.f32 "
        "{%0,%1,%2,%3}, {%4,%5,%6,%7}, {%8,%9}, {%0,%1,%2,%3};"
        : "+f"(d[0]), "+f"(d[1]), "+f"(d[2]), "+f"(d[3])
        : "r"(a[0]), "r"(a[1]), "r"(a[2]), "r"(a[3]), "r"(b[0]), "r"(b[1]));
}
__device__ __forceinline__ int perm64(int c) {       // c in 0..63
    return (c & 32) + ((c & 3) << 3) + ((c >> 2) & 7);
}

// ==========================================================================
// Kernel 0: permute W (tf32) into g_wp[mat][k][pn], pn = (n&7)*8 + (n>>3).
// ==========================================================================
__global__ __launch_bounds__(256) void wperm(
    const float* __restrict__ Wq, const float* __restrict__ Wk,
    const float* __restrict__ Wv)
{
    const int mat = blockIdx.y;
    const float* W = (mat == 0) ? Wq : (mat == 1) ? Wk : Wv;
    float* dst = g_wp + mat * (EE*HH);
    #pragma unroll
    for (int i = 0; i < 8; i++) {
        int idx = blockIdx.x * 2048 + i*256 + threadIdx.x;
        int k = idx >> 6, n = idx & 63;
        dst[k*64 + ((n & 7) << 3) + (n >> 3)] = tf32r(W[idx]);
    }
}

// ==========================================================================
// Kernel 1: QKV projection (round-12 winner, unchanged). One matrix per
// blockIdx.y. Block 128 thr (4 warps x 32 rows = 2 m-tiles; B-frags reused).
// ==========================================================================
#define QK_XST 36
#define QK_WST 68

__global__ __launch_bounds__(128) void qkv_proj(
    const float* __restrict__ x,
    const float* __restrict__ bq, const float* __restrict__ bk,
    const float* __restrict__ bv)
{
    __shared__ float xs[128*QK_XST];      // natural [row][k], 18.4 KB
    __shared__ float ws[32*QK_WST];       // permuted [k][pn], 8.7 KB

    const int tid  = threadIdx.x;
    const int warp = tid >> 5;
    const int lane = tid & 31;
    const int g    = lane >> 2;
    const int tig  = lane & 3;
    const int row0 = blockIdx.x * 128;
    const int mat  = blockIdx.y;

    const float* wp   = g_wp + mat * (EE*HH);
    const float* bias = (mat == 0) ? bq : (mat == 1) ? bk : bv;

    float4 xt[8], wt[4];
    #pragma unroll
    for (int i = 0; i < 8; i++) {
        int f4 = i*128 + tid;
        xt[i] = *(const float4*)&x[(size_t)(row0 + (f4>>3))*EE + (f4&7)*4];
    }
    #pragma unroll
    for (int i = 0; i < 4; i++) {
        int f4 = i*128 + tid;
        wt[i] = *(const float4*)&wp[(size_t)(f4>>4)*64 + (f4&15)*4];
    }

    float acc[2][8][4] = {};

    #pragma unroll 1
    for (int kb = 0; kb < EE; kb += 32) {
        #pragma unroll
        for (int i = 0; i < 8; i++) {
            int f4 = i*128 + tid;
            int r = f4 >> 3, c4 = f4 & 7;
            float4 t;
            t.x = tf32r(xt[i].x); t.y = tf32r(xt[i].y);
            t.z = tf32r(xt[i].z); t.w = tf32r(xt[i].w);
            *(float4*)&xs[r*QK_XST + c4*4] = t;
        }
        #pragma unroll
        for (int i = 0; i < 4; i++) {
            int f4 = i*128 + tid;
            *(float4*)&ws[(f4>>4)*QK_WST + (f4&15)*4] = wt[i];
        }
        __syncthreads();

        if (kb + 32 < EE) {
            #pragma unroll
            for (int i = 0; i < 8; i++) {
                int f4 = i*128 + tid;
                xt[i] = *(const float4*)&x[(size_t)(row0 + (f4>>3))*EE + kb+32 + (f4&7)*4];
            }
            #pragma unroll
            for (int i = 0; i < 4; i++) {
                int f4 = i*128 + tid;
                wt[i] = *(const float4*)&wp[(size_t)(kb+32 + (f4>>4))*64 + (f4&15)*4];
            }
        }

        #pragma unroll
        for (int ks = 0; ks < 4; ks++) {
            float w1[8], w2[8];
            *(float4*)&w1[0] = *(const float4*)&ws[(8*ks+tig  )*QK_WST + g*8    ];
            *(float4*)&w1[4] = *(const float4*)&ws[(8*ks+tig  )*QK_WST + g*8 + 4];
            *(float4*)&w2[0] = *(const float4*)&ws[(8*ks+tig+4)*QK_WST + g*8    ];
            *(float4*)&w2[4] = *(const float4*)&ws[(8*ks+tig+4)*QK_WST + g*8 + 4];
            #pragma unroll
            for (int mt = 0; mt < 2; mt++) {
                const int rb = warp*32 + mt*16 + g;
                uint32_t a[4];
                a[0] = __float_as_uint(xs[ rb   *QK_XST + 8*ks + tig    ]);
                a[1] = __float_as_uint(xs[(rb+8)*QK_XST + 8*ks + tig    ]);
                a[2] = __float_as_uint(xs[ rb   *QK_XST + 8*ks + tig + 4]);
                a[3] = __float_as_uint(xs[(rb+8)*QK_XST + 8*ks + tig + 4]);
                #pragma unroll
                for (int nt = 0; nt < 8; nt++) {
                    uint32_t bf[2] = { __float_as_uint(w1[nt]), __float_as_uint(w2[nt]) };
                    mma_tf32(acc[mt][nt], a, bf);
                }
            }
        }
        __syncthreads();
    }

    #pragma unroll
    for (int mt = 0; mt < 2; mt++) {
        const int rowa = row0 + warp*32 + mt*16 + g;
        const int rowb = rowa + 8;
        #pragma unroll
        for (int nt = 0; nt < 8; nt++) {
            const int col = nt*8 + 2*tig;
            const float b0 = __ldg(&bias[col]);
            const float b1 = __ldg(&bias[col+1]);
            float v0 = acc[mt][nt][0] + b0, v1 = acc[mt][nt][1] + b1;
            float v2 = acc[mt][nt][2] + b0, v3 = acc[mt][nt][3] + b1;
            if (mat == 0) {            // Q: scale + tf32 + e-permuted
                const int p = perm64(col);
                g_q[(size_t)rowa*HH + p]     = tf32r(v0 * 0.125f);
                g_q[(size_t)rowa*HH + p + 8] = tf32r(v1 * 0.125f);
                g_q[(size_t)rowb*HH + p]     = tf32r(v2 * 0.125f);
                g_q[(size_t)rowb*HH + p + 8] = tf32r(v3 * 0.125f);
            } else if (mat == 1) {     // K: tf32 + e-permuted
                const int p = perm64(col);
                g_k[(size_t)rowa*HH + p]     = tf32r(v0);
                g_k[(size_t)rowa*HH + p + 8] = tf32r(v1);
                g_k[(size_t)rowb*HH + p]     = tf32r(v2);
                g_k[(size_t)rowb*HH + p + 8] = tf32r(v3);
            } else {                   // V: tf32, transposed, key tile-permuted
                const size_t ta = (size_t)(rowa & ~63) + perm64(rowa & 63);
                const size_t tb = (size_t)(rowb & ~63) + perm64(rowb & 63);
                g_vt[(size_t) col   *NROWS + ta] = tf32r(v0);
                g_vt[(size_t)(col+1)*NROWS + ta] = tf32r(v1);
                g_vt[(size_t) col   *NROWS + tb] = tf32r(v2);
                g_vt[(size_t)(col+1)*NROWS + tb] = tf32r(v3);
            }
        }
    }
}

// ==========================================================================
// Kernel 2: split-K causal flash attention. CHANGE vs round 12:
// P gets its OWN buffer (no K overlay) -> the pre-P-write __syncthreads
// disappears, and the post-P-write barrier becomes __syncwarp (warp writes
// and reads only its own 16 Ps rows). 2 block barriers/subtile instead of 4.
// smem: Qs | Ks | Vst | Ps = 4 x 64 x 68 floats = 69.6 KB (3 CTAs/SM).
// ==========================================================================
#define AST 68
#define ATTN_SMEM (4*64*AST*4)   // 69,632 B

__global__ __launch_bounds__(128) void attn_partial()
{
    extern __shared__ float dsm[];
    float* Qs  = dsm;
    float* Ks  = dsm + 64*AST;
    float* Vst = dsm + 2*64*AST;
    float* Ps  = dsm + 3*64*AST;

    const int tid  = threadIdx.x;
    const int warp = tid >> 5;
    const int lane = tid & 31;
    const int g    = lane >> 2;
    const int tig  = lane & 3;
    const int qt   = blockIdx.x;
    const int c    = blockIdx.y;
    const int b    = blockIdx.z;
    if (4*c > qt) return;

    const int q0 = qt * 64;
    const int wq = warp * 16;

    // ---- stage Q: pure copy ----
    #pragma unroll
    for (int i = 0; i < 8; i++) {
        int f4 = i*128 + tid;
        int r = f4 >> 4, c4 = f4 & 15;
        *(float4*)&Qs[r*AST + c4*4] =
            *(const float4*)&g_q[((size_t)b*SS + q0 + r)*HH + c4*4];
    }

    float O[8][4] = {};
    float m0 = -CUDART_INF_F, m1 = -CUDART_INF_F;
    float l0 = 0.0f, l1 = 0.0f;

    #pragma unroll 1
    for (int sub = 0; sub < 4; sub++) {
        const int k0 = c*CH + sub*64;
        if (k0 > q0) break;
        const bool diag = (k0 == q0);

        __syncthreads();                  // prior Phase A/B reads of Ks/Vst done
        // ---- stage K: pure copy ----
        #pragma unroll
        for (int i = 0; i < 8; i++) {
            int f4 = i*128 + tid;
            int r = f4 >> 4, c4 = f4 & 15;
            *(float4*)&Ks[r*AST + c4*4] =
                *(const float4*)&g_k[((size_t)b*SS + k0 + r)*HH + c4*4];
        }
        // ---- stage V: pure copy from transposed g_vt ----
        #pragma unroll
        for (int i = 0; i < 8; i++) {
            int f4 = i*128 + tid;
            int h = f4 >> 4, j4 = f4 & 15;
            *(float4*)&Vst[h*AST + j4*4] =
                *(const float4*)&g_vt[(size_t)h*NROWS + (size_t)b*SS + k0 + j4*4];
        }
        __syncthreads();

        // ---- Phase A: S = Qhat Khat^T ----
        float S[8][4] = {};
        #pragma unroll
        for (int eb = 0; eb < 2; eb++) {
            float al[8], ah[8];
            *(float4*)&al[0] = *(const float4*)&Qs[(wq+g  )*AST + eb*32 + tig*8    ];
            *(float4*)&al[4] = *(const float4*)&Qs[(wq+g  )*AST + eb*32 + tig*8 + 4];
            *(float4*)&ah[0] = *(const float4*)&Qs[(wq+g+8)*AST + eb*32 + tig*8    ];
            *(float4*)&ah[4] = *(const float4*)&Qs[(wq+g+8)*AST + eb*32 + tig*8 + 4];
            #pragma unroll
            for (int nh = 0; nh < 2; nh++) {
                float kv[4][8];
                #pragma unroll
                for (int j = 0; j < 4; j++) {
                    int nt = nh*4 + j;
                    *(float4*)&kv[j][0] = *(const float4*)&Ks[(nt*8+g)*AST + eb*32 + tig*8    ];
                    *(float4*)&kv[j][4] = *(const float4*)&Ks[(nt*8+g)*AST + eb*32 + tig*8 + 4];
                }
                #pragma unroll
                for (int k2 = 0; k2 < 4; k2++) {
                    uint32_t a[4];
                    a[0] = __float_as_uint(al[2*k2  ]);
                    a[1] = __float_as_uint(ah[2*k2  ]);
                    a[2] = __float_as_uint(al[2*k2+1]);
                    a[3] = __float_as_uint(ah[2*k2+1]);
                    #pragma unroll
                    for (int j = 0; j < 4; j++) {
                        uint32_t bf[2] = { __float_as_uint(kv[j][2*k2]),
                                           __float_as_uint(kv[j][2*k2+1]) };
                        mma_tf32(S[nh*4+j], a, bf);
                    }
                }
            }
        }

        // ---- causal mask (diagonal subtile only) ----
        const int gq0 = q0 + wq + g;
        const int gq1 = gq0 + 8;
        if (diag) {
            #pragma unroll
            for (int nt = 0; nt < 8; nt++) {
                const int kc = k0 + nt*8 + 2*tig;
                if (kc   > gq0) S[nt][0] = -CUDART_INF_F;
                if (kc+1 > gq0) S[nt][1] = -CUDART_INF_F;
                if (kc   > gq1) S[nt][2] = -CUDART_INF_F;
                if (kc+1 > gq1) S[nt][3] = -CUDART_INF_F;
            }
        }

        // ---- online softmax (quad shfl) ----
        float mx0 = -CUDART_INF_F, mx1 = -CUDART_INF_F;
        #pragma unroll
        for (int nt = 0; nt < 8; nt++) {
            mx0 = fmaxf(mx0, fmaxf(S[nt][0], S[nt][1]));
            mx1 = fmaxf(mx1, fmaxf(S[nt][2], S[nt][3]));
        }
        mx0 = fmaxf(mx0, __shfl_xor_sync(0xffffffffu, mx0, 1));
        mx0 = fmaxf(mx0, __shfl_xor_sync(0xffffffffu, mx0, 2));
        mx1 = fmaxf(mx1, __shfl_xor_sync(0xffffffffu, mx1, 1));
        mx1 = fmaxf(mx1, __shfl_xor_sync(0xffffffffu, mx1, 2));

        const float nm0 = fmaxf(m0, mx0), nm1 = fmaxf(m1, mx1);
        const float al0 = __expf(m0 - nm0), al1 = __expf(m1 - nm1);
        m0 = nm0; m1 = nm1;

        float s0 = 0.0f, s1 = 0.0f;
        #pragma unroll
        for (int nt = 0; nt < 8; nt++) {
            S[nt][0] = __expf(S[nt][0] - nm0);
            S[nt][1] = __expf(S[nt][1] - nm0);
            S[nt][2] = __expf(S[nt][2] - nm1);
            S[nt][3] = __expf(S[nt][3] - nm1);
            s0 += S[nt][0] + S[nt][1];
            s1 += S[nt][2] + S[nt][3];
        }
        s0 += __shfl_xor_sync(0xffffffffu, s0, 1);
        s0 += __shfl_xor_sync(0xffffffffu, s0, 2);
        s1 += __shfl_xor_sync(0xffffffffu, s1, 1);
        s1 += __shfl_xor_sync(0xffffffffu, s1, 2);
        l0 = l0*al0 + s0;
        l1 = l1*al1 + s1;
        #pragma unroll
        for (int nt = 0; nt < 8; nt++) {
            O[nt][0] *= al0; O[nt][1] *= al0;
            O[nt][2] *= al1; O[nt][3] *= al1;
        }

        // ---- stage P (own buffer; rows wq..wq+15 are warp-private) ----
        #pragma unroll
        for (int nt = 0; nt < 8; nt++) {
            const int p0 = perm64(nt*8 + 2*tig);
            Ps[(wq+g  )*AST + p0    ] = tf32r(S[nt][0]);
            Ps[(wq+g  )*AST + p0 + 8] = tf32r(S[nt][1]);
            Ps[(wq+g+8)*AST + p0    ] = tf32r(S[nt][2]);
            Ps[(wq+g+8)*AST + p0 + 8] = tf32r(S[nt][3]);
        }
        __syncwarp();                     // producer/consumer = same warp

        // ---- Phase B: O += P V ----
        #pragma unroll
        for (int kb = 0; kb < 2; kb++) {
            float al2[8], ah2[8];
            *(float4*)&al2[0] = *(const float4*)&Ps[(wq+g  )*AST + kb*32 + tig*8    ];
            *(float4*)&al2[4] = *(const float4*)&Ps[(wq+g  )*AST + kb*32 + tig*8 + 4];
            *(float4*)&ah2[0] = *(const float4*)&Ps[(wq+g+8)*AST + kb*32 + tig*8    ];
            *(float4*)&ah2[4] = *(const float4*)&Ps[(wq+g+8)*AST + kb*32 + tig*8 + 4];
            #pragma unroll
            for (int nh = 0; nh < 2; nh++) {
                float vv[4][8];
                #pragma unroll
                for (int j = 0; j < 4; j++) {
                    int nt = nh*4 + j;
                    *(float4*)&vv[j][0] = *(const float4*)&Vst[(nt*8+g)*AST + kb*32 + tig*8    ];
                    *(float4*)&vv[j][4] = *(const float4*)&Vst[(nt*8+g)*AST + kb*32 + tig*8 + 4];
                }
                #pragma unroll
                for (int k2 = 0; k2 < 4; k2++) {
                    uint32_t a[4];
                    a[0] = __float_as_uint(al2[2*k2  ]);
                    a[1] = __float_as_uint(ah2[2*k2  ]);
                    a[2] = __float_as_uint(al2[2*k2+1]);
                    a[3] = __float_as_uint(ah2[2*k2+1]);
                    #pragma unroll
                    for (int j = 0; j < 4; j++) {
                        uint32_t bf[2] = { __float_as_uint(vv[j][2*k2]),
                                           __float_as_uint(vv[j][2*k2+1]) };
                        mma_tf32(O[nh*4+j], a, bf);
                    }
                }
            }
        }
    }

    // ---- write unnormalized partials + (m, l) ----
    const size_t r0 = (size_t)b*SS + q0 + wq + g;
    const size_t r1 = r0 + 8;
    #pragma unroll
    for (int nt = 0; nt < 8; nt++) {
        const int col = nt*8 + 2*tig;
        *(float2*)&g_opart[(r0*NCH + c)*HH + col] = make_float2(O[nt][0], O[nt][1]);
        *(float2*)&g_opart[(r1*NCH + c)*HH + col] = make_float2(O[nt][2], O[nt][3]);
    }
    if (tig == 0) {
        g_ml[(r0*NCH + c)*2 + 0] = m0;
        g_ml[(r0*NCH + c)*2 + 1] = l0;
        g_ml[(r1*NCH + c)*2 + 0] = m1;
        g_ml[(r1*NCH + c)*2 + 1] = l1;
    }
}

// ==========================================================================
// Kernel 3: combine. Fixed fully-unrolled 8-chunk loop (zero-init chunks
// contribute nothing; max over extra zeros only shifts normalization).
// ==========================================================================
__global__ __launch_bounds__(64) void attn_combine(float* __restrict__ out)
{
    const size_t r = blockIdx.x;
    const int    e = threadIdx.x;

    float mc[NCH], lc[NCH], op[NCH];
    #pragma unroll
    for (int c = 0; c < NCH; c++) {
        float2 ml = *(const float2*)&g_ml[(r*NCH + c)*2];
        mc[c] = ml.x; lc[c] = ml.y;
        op[c] = g_opart[(r*NCH + c)*HH + e];
    }
    float M = mc[0];
    #pragma unroll
    for (int c = 1; c < NCH; c++) M = fmaxf(M, mc[c]);

    float L = 0.0f, o = 0.0f;
    #pragma unroll
    for (int c = 0; c < NCH; c++) {
        float w = __expf(mc[c] - M);
        L += lc[c] * w;
        o  = fmaf(w, op[c], o);
    }
    out[r*HH + e] = o / L;
}

// ==========================================================================
extern "C" void kernel_launch(void* const* d_in, const int* in_sizes, int n_in,
                              void* d_out, int out_size)
{
    const float* x  = (const float*)d_in[0];
    const float* Wq = (const float*)d_in[1];
    const float* bq = (const float*)d_in[2];
    const float* Wk = (const float*)d_in[3];
    const float* bk = (const float*)d_in[4];
    const float* Wv = (const float*)d_in[5];
    const float* bv = (const float*)d_in[6];
    float* out = (float*)d_out;

    cudaFuncSetAttribute(attn_partial,
                         cudaFuncAttributeMaxDynamicSharedMemorySize, ATTN_SMEM);

    dim3 gw(32, 3);
    wperm<<<gw, 256>>>(Wq, Wk, Wv);

    dim3 gq(NROWS / 128, 3);
    qkv_proj<<<gq, 128>>>(x, bq, bk, bv);

    dim3 ga(SS / 64, NCH, BB);
    attn_partial<<<ga, 128, ATTN_SMEM>>>();

    attn_combine<<<NROWS, 64>>>(out);
}

// round 15
// speedup vs baseline: 1.1058x; 1.0489x over previous
#include <cuda_runtime.h>
#include <math_constants.h>
#include <cstdint>
#include <cstddef>

// Problem shape (fixed by reference)
#define BB  4
#define SS  2048
#define EE  1024
#define HH  64
#define NROWS (BB*SS)     // 8192 query rows
#define CH  256           // keys per split-K chunk (four 64-key subtiles)
#define NCH (SS/CH)       // 8 chunks per batch

// -------- device scratch (no allocations allowed; zero-initialized) --------
__device__ float g_q[NROWS*HH];                  // tf32, e-permuted, pre-scaled
__device__ float g_k[NROWS*HH];                  // tf32, e-permuted
__device__ float g_vt[HH*NROWS];                 // tf32, transposed, tile-permuted
__device__ float g_wp[3*EE*HH];                  // pre-permuted tf32 W (768KB)
__device__ float g_opart[(size_t)NROWS*NCH*HH];  // zero-init matters (combine)
__device__ float g_ml[(size_t)NROWS*NCH*2];      // zero-init matters

// -------- tf32 helpers --------
__device__ __forceinline__ float tf32r(float x) {
    uint32_t u;
    asm("cvt.rna.tf32.f32 %0, %1;" : "=r"(u) : "f"(x));
    return __uint_as_float(u);
}
__device__ __forceinline__ void mma_tf32(float* d, const uint32_t* a, const uint32_t* b) {
    asm volatile(
        "mma.sync.aligned.m16n8k8.row.col.f32.tf32.tf32.f32 "
        "{%0,%1,%2,%3}, {%4,%5,%6,%7}, {%8,%9}, {%0,%1,%2,%3};"
        : "+f"(d[0]), "+f"(d[1]), "+f"(d[2]), "+f"(d[3])
        : "r"(a[0]), "r"(a[1]), "r"(a[2]), "r"(a[3]), "r"(b[0]), "r"(b[1]));
}
__device__ __forceinline__ int perm64(int c) {       // c in 0..63
    return (c & 32) + ((c & 3) << 3) + ((c >> 2) & 7);
}

// ==========================================================================
// Kernel 0: permute W (tf32) into g_wp[mat][k][pn], pn = (n&7)*8 + (n>>3).
// ==========================================================================
__global__ __launch_bounds__(256) void wperm(
    const float* __restrict__ Wq, const float* __restrict__ Wk,
    const float* __restrict__ Wv)
{
    const int mat = blockIdx.y;
    const float* W = (mat == 0) ? Wq : (mat == 1) ? Wk : Wv;
    float* dst = g_wp + mat * (EE*HH);
    #pragma unroll
    for (int i = 0; i < 8; i++) {
        int idx = blockIdx.x * 2048 + i*256 + threadIdx.x;
        int k = idx >> 6, n = idx & 63;
        dst[k*64 + ((n & 7) << 3) + (n >> 3)] = tf32r(W[idx]);
    }
}

// ==========================================================================
// Kernel 1: QKV projection (round-12 winner, unchanged). One matrix per
// blockIdx.y. Block 128 thr (4 warps x 32 rows = 2 m-tiles; B-frags reused).
// ==========================================================================
#define QK_XST 36
#define QK_WST 68

__global__ __launch_bounds__(128) void qkv_proj(
    const float* __restrict__ x,
    const float* __restrict__ bq, const float* __restrict__ bk,
    const float* __restrict__ bv)
{
    __shared__ float xs[128*QK_XST];      // natural [row][k], 18.4 KB
    __shared__ float ws[32*QK_WST];       // permuted [k][pn], 8.7 KB

    const int tid  = threadIdx.x;
    const int warp = tid >> 5;
    const int lane = tid & 31;
    const int g    = lane >> 2;
    const int tig  = lane & 3;
    const int row0 = blockIdx.x * 128;
    const int mat  = blockIdx.y;

    const float* wp   = g_wp + mat * (EE*HH);
    const float* bias = (mat == 0) ? bq : (mat == 1) ? bk : bv;

    float4 xt[8], wt[4];
    #pragma unroll
    for (int i = 0; i < 8; i++) {
        int f4 = i*128 + tid;
        xt[i] = *(const float4*)&x[(size_t)(row0 + (f4>>3))*EE + (f4&7)*4];
    }
    #pragma unroll
    for (int i = 0; i < 4; i++) {
        int f4 = i*128 + tid;
        wt[i] = *(const float4*)&wp[(size_t)(f4>>4)*64 + (f4&15)*4];
    }

    float acc[2][8][4] = {};

    #pragma unroll 1
    for (int kb = 0; kb < EE; kb += 32) {
        #pragma unroll
        for (int i = 0; i < 8; i++) {
            int f4 = i*128 + tid;
            int r = f4 >> 3, c4 = f4 & 7;
            float4 t;
            t.x = tf32r(xt[i].x); t.y = tf32r(xt[i].y);
            t.z = tf32r(xt[i].z); t.w = tf32r(xt[i].w);
            *(float4*)&xs[r*QK_XST + c4*4] = t;
        }
        #pragma unroll
        for (int i = 0; i < 4; i++) {
            int f4 = i*128 + tid;
            *(float4*)&ws[(f4>>4)*QK_WST + (f4&15)*4] = wt[i];
        }
        __syncthreads();

        if (kb + 32 < EE) {
            #pragma unroll
            for (int i = 0; i < 8; i++) {
                int f4 = i*128 + tid;
                xt[i] = *(const float4*)&x[(size_t)(row0 + (f4>>3))*EE + kb+32 + (f4&7)*4];
            }
            #pragma unroll
            for (int i = 0; i < 4; i++) {
                int f4 = i*128 + tid;
                wt[i] = *(const float4*)&wp[(size_t)(kb+32 + (f4>>4))*64 + (f4&15)*4];
            }
        }

        #pragma unroll
        for (int ks = 0; ks < 4; ks++) {
            float w1[8], w2[8];
            *(float4*)&w1[0] = *(const float4*)&ws[(8*ks+tig  )*QK_WST + g*8    ];
            *(float4*)&w1[4] = *(const float4*)&ws[(8*ks+tig  )*QK_WST + g*8 + 4];
            *(float4*)&w2[0] = *(const float4*)&ws[(8*ks+tig+4)*QK_WST + g*8    ];
            *(float4*)&w2[4] = *(const float4*)&ws[(8*ks+tig+4)*QK_WST + g*8 + 4];
            #pragma unroll
            for (int mt = 0; mt < 2; mt++) {
                const int rb = warp*32 + mt*16 + g;
                uint32_t a[4];
                a[0] = __float_as_uint(xs[ rb   *QK_XST + 8*ks + tig    ]);
                a[1] = __float_as_uint(xs[(rb+8)*QK_XST + 8*ks + tig    ]);
                a[2] = __float_as_uint(xs[ rb   *QK_XST + 8*ks + tig + 4]);
                a[3] = __float_as_uint(xs[(rb+8)*QK_XST + 8*ks + tig + 4]);
                #pragma unroll
                for (int nt = 0; nt < 8; nt++) {
                    uint32_t bf[2] = { __float_as_uint(w1[nt]), __float_as_uint(w2[nt]) };
                    mma_tf32(acc[mt][nt], a, bf);
                }
            }
        }
        __syncthreads();
    }

    #pragma unroll
    for (int mt = 0; mt < 2; mt++) {
        const int rowa = row0 + warp*32 + mt*16 + g;
        const int rowb = rowa + 8;
        #pragma unroll
        for (int nt = 0; nt < 8; nt++) {
            const int col = nt*8 + 2*tig;
            const float b0 = __ldg(&bias[col]);
            const float b1 = __ldg(&bias[col+1]);
            float v0 = acc[mt][nt][0] + b0, v1 = acc[mt][nt][1] + b1;
            float v2 = acc[mt][nt][2] + b0, v3 = acc[mt][nt][3] + b1;
            if (mat == 0) {            // Q: scale + tf32 + e-permuted
                const int p = perm64(col);
                g_q[(size_t)rowa*HH + p]     = tf32r(v0 * 0.125f);
                g_q[(size_t)rowa*HH + p + 8] = tf32r(v1 * 0.125f);
                g_q[(size_t)rowb*HH + p]     = tf32r(v2 * 0.125f);
                g_q[(size_t)rowb*HH + p + 8] = tf32r(v3 * 0.125f);
            } else if (mat == 1) {     // K: tf32 + e-permuted
                const int p = perm64(col);
                g_k[(size_t)rowa*HH + p]     = tf32r(v0);
                g_k[(size_t)rowa*HH + p + 8] = tf32r(v1);
                g_k[(size_t)rowb*HH + p]     = tf32r(v2);
                g_k[(size_t)rowb*HH + p + 8] = tf32r(v3);
            } else {                   // V: tf32, transposed, key tile-permuted
                const size_t ta = (size_t)(rowa & ~63) + perm64(rowa & 63);
                const size_t tb = (size_t)(rowb & ~63) + perm64(rowb & 63);
                g_vt[(size_t) col   *NROWS + ta] = tf32r(v0);
                g_vt[(size_t)(col+1)*NROWS + ta] = tf32r(v1);
                g_vt[(size_t) col   *NROWS + tb] = tf32r(v2);
                g_vt[(size_t)(col+1)*NROWS + tb] = tf32r(v3);
            }
        }
    }
}

// ==========================================================================
// Kernel 2: split-K causal flash attention (round-12 structure: P overlays
// K, 52.2 KB smem -> 4 CTAs/SM). ONE change: the post-P-write barrier is
// __syncwarp, not __syncthreads — warp w writes and reads only Ps rows
// wq..wq+15; the loop-top __syncthreads already orders P reads vs the next
// subtile's K staging. 3 block barriers per subtile instead of 4.
// ==========================================================================
#define AST 68
#define ATTN_SMEM (3*64*AST*4)   // 52.2 KB

__global__ __launch_bounds__(128) void attn_partial()
{
    extern __shared__ float dsm[];
    float* Qs  = dsm;
    float* KPs = dsm + 64*AST;
    float* Vst = dsm + 2*64*AST;

    const int tid  = threadIdx.x;
    const int warp = tid >> 5;
    const int lane = tid & 31;
    const int g    = lane >> 2;
    const int tig  = lane & 3;
    const int qt   = blockIdx.x;
    const int c    = blockIdx.y;
    const int b    = blockIdx.z;
    if (4*c > qt) return;

    const int q0 = qt * 64;
    const int wq = warp * 16;

    // ---- stage Q: pure copy ----
    #pragma unroll
    for (int i = 0; i < 8; i++) {
        int f4 = i*128 + tid;
        int r = f4 >> 4, c4 = f4 & 15;
        *(float4*)&Qs[r*AST + c4*4] =
            *(const float4*)&g_q[((size_t)b*SS + q0 + r)*HH + c4*4];
    }

    float O[8][4] = {};
    float m0 = -CUDART_INF_F, m1 = -CUDART_INF_F;
    float l0 = 0.0f, l1 = 0.0f;

    #pragma unroll 1
    for (int sub = 0; sub < 4; sub++) {
        const int k0 = c*CH + sub*64;
        if (k0 > q0) break;
        const bool diag = (k0 == q0);

        __syncthreads();                  // prior subtile's P/V reads done
        // ---- stage K: pure copy ----
        #pragma unroll
        for (int i = 0; i < 8; i++) {
            int f4 = i*128 + tid;
            int r = f4 >> 4, c4 = f4 & 15;
            *(float4*)&KPs[r*AST + c4*4] =
                *(const float4*)&g_k[((size_t)b*SS + k0 + r)*HH + c4*4];
        }
        // ---- stage V: pure copy from transposed g_vt ----
        #pragma unroll
        for (int i = 0; i < 8; i++) {
            int f4 = i*128 + tid;
            int h = f4 >> 4, j4 = f4 & 15;
            *(float4*)&Vst[h*AST + j4*4] =
                *(const float4*)&g_vt[(size_t)h*NROWS + (size_t)b*SS + k0 + j4*4];
        }
        __syncthreads();

        // ---- Phase A: S = Qhat Khat^T ----
        float S[8][4] = {};
        #pragma unroll
        for (int eb = 0; eb < 2; eb++) {
            float al[8], ah[8];
            *(float4*)&al[0] = *(const float4*)&Qs[(wq+g  )*AST + eb*32 + tig*8    ];
            *(float4*)&al[4] = *(const float4*)&Qs[(wq+g  )*AST + eb*32 + tig*8 + 4];
            *(float4*)&ah[0] = *(const float4*)&Qs[(wq+g+8)*AST + eb*32 + tig*8    ];
            *(float4*)&ah[4] = *(const float4*)&Qs[(wq+g+8)*AST + eb*32 + tig*8 + 4];
            #pragma unroll
            for (int nh = 0; nh < 2; nh++) {
                float kv[4][8];
                #pragma unroll
                for (int j = 0; j < 4; j++) {
                    int nt = nh*4 + j;
                    *(float4*)&kv[j][0] = *(const float4*)&KPs[(nt*8+g)*AST + eb*32 + tig*8    ];
                    *(float4*)&kv[j][4] = *(const float4*)&KPs[(nt*8+g)*AST + eb*32 + tig*8 + 4];
                }
                #pragma unroll
                for (int k2 = 0; k2 < 4; k2++) {
                    uint32_t a[4];
                    a[0] = __float_as_uint(al[2*k2  ]);
                    a[1] = __float_as_uint(ah[2*k2  ]);
                    a[2] = __float_as_uint(al[2*k2+1]);
                    a[3] = __float_as_uint(ah[2*k2+1]);
                    #pragma unroll
                    for (int j = 0; j < 4; j++) {
                        uint32_t bf[2] = { __float_as_uint(kv[j][2*k2]),
                                           __float_as_uint(kv[j][2*k2+1]) };
                        mma_tf32(S[nh*4+j], a, bf);
                    }
                }
            }
        }

        // ---- causal mask (diagonal subtile only) ----
        const int gq0 = q0 + wq + g;
        const int gq1 = gq0 + 8;
        if (diag) {
            #pragma unroll
            for (int nt = 0; nt < 8; nt++) {
                const int kc = k0 + nt*8 + 2*tig;
                if (kc   > gq0) S[nt][0] = -CUDART_INF_F;
                if (kc+1 > gq0) S[nt][1] = -CUDART_INF_F;
                if (kc   > gq1) S[nt][2] = -CUDART_INF_F;
                if (kc+1 > gq1) S[nt][3] = -CUDART_INF_F;
            }
        }

        // ---- online softmax (quad shfl) ----
        float mx0 = -CUDART_INF_F, mx1 = -CUDART_INF_F;
        #pragma unroll
        for (int nt = 0; nt < 8; nt++) {
            mx0 = fmaxf(mx0, fmaxf(S[nt][0], S[nt][1]));
            mx1 = fmaxf(mx1, fmaxf(S[nt][2], S[nt][3]));
        }
        mx0 = fmaxf(mx0, __shfl_xor_sync(0xffffffffu, mx0, 1));
        mx0 = fmaxf(mx0, __shfl_xor_sync(0xffffffffu, mx0, 2));
        mx1 = fmaxf(mx1, __shfl_xor_sync(0xffffffffu, mx1, 1));
        mx1 = fmaxf(mx1, __shfl_xor_sync(0xffffffffu, mx1, 2));

        const float nm0 = fmaxf(m0, mx0), nm1 = fmaxf(m1, mx1);
        const float al0 = __expf(m0 - nm0), al1 = __expf(m1 - nm1);
        m0 = nm0; m1 = nm1;

        float s0 = 0.0f, s1 = 0.0f;
        #pragma unroll
        for (int nt = 0; nt < 8; nt++) {
            S[nt][0] = __expf(S[nt][0] - nm0);
            S[nt][1] = __expf(S[nt][1] - nm0);
            S[nt][2] = __expf(S[nt][2] - nm1);
            S[nt][3] = __expf(S[nt][3] - nm1);
            s0 += S[nt][0] + S[nt][1];
            s1 += S[nt][2] + S[nt][3];
        }
        s0 += __shfl_xor_sync(0xffffffffu, s0, 1);
        s0 += __shfl_xor_sync(0xffffffffu, s0, 2);
        s1 += __shfl_xor_sync(0xffffffffu, s1, 1);
        s1 += __shfl_xor_sync(0xffffffffu, s1, 2);
        l0 = l0*al0 + s0;
        l1 = l1*al1 + s1;
        #pragma unroll
        for (int nt = 0; nt < 8; nt++) {
            O[nt][0] *= al0; O[nt][1] *= al0;
            O[nt][2] *= al1; O[nt][3] *= al1;
        }

        __syncthreads();                  // all warps done reading K
        // ---- stage P over K region (tf32, key-permuted) ----
        #pragma unroll
        for (int nt = 0; nt < 8; nt++) {
            const int p0 = perm64(nt*8 + 2*tig);
            KPs[(wq+g  )*AST + p0    ] = tf32r(S[nt][0]);
            KPs[(wq+g  )*AST + p0 + 8] = tf32r(S[nt][1]);
            KPs[(wq+g+8)*AST + p0    ] = tf32r(S[nt][2]);
            KPs[(wq+g+8)*AST + p0 + 8] = tf32r(S[nt][3]);
        }
        __syncwarp();                     // Phase B reads only this warp's rows

        // ---- Phase B: O += P V ----
        #pragma unroll
        for (int kb = 0; kb < 2; kb++) {
            float al2[8], ah2[8];
            *(float4*)&al2[0] = *(const float4*)&KPs[(wq+g  )*AST + kb*32 + tig*8    ];
            *(float4*)&al2[4] = *(const float4*)&KPs[(wq+g  )*AST + kb*32 + tig*8 + 4];
            *(float4*)&ah2[0] = *(const float4*)&KPs[(wq+g+8)*AST + kb*32 + tig*8    ];
            *(float4*)&ah2[4] = *(const float4*)&KPs[(wq+g+8)*AST + kb*32 + tig*8 + 4];
            #pragma unroll
            for (int nh = 0; nh < 2; nh++) {
                float vv[4][8];
                #pragma unroll
                for (int j = 0; j < 4; j++) {
                    int nt = nh*4 + j;
                    *(float4*)&vv[j][0] = *(const float4*)&Vst[(nt*8+g)*AST + kb*32 + tig*8    ];
                    *(float4*)&vv[j][4] = *(const float4*)&Vst[(nt*8+g)*AST + kb*32 + tig*8 + 4];
                }
                #pragma unroll
                for (int k2 = 0; k2 < 4; k2++) {
                    uint32_t a[4];
                    a[0] = __float_as_uint(al2[2*k2  ]);
                    a[1] = __float_as_uint(ah2[2*k2  ]);
                    a[2] = __float_as_uint(al2[2*k2+1]);
                    a[3] = __float_as_uint(ah2[2*k2+1]);
                    #pragma unroll
                    for (int j = 0; j < 4; j++) {
                        uint32_t bf[2] = { __float_as_uint(vv[j][2*k2]),
                                           __float_as_uint(vv[j][2*k2+1]) };
                        mma_tf32(O[nh*4+j], a, bf);
                    }
                }
            }
        }
    }

    // ---- write unnormalized partials + (m, l) ----
    const size_t r0 = (size_t)b*SS + q0 + wq + g;
    const size_t r1 = r0 + 8;
    #pragma unroll
    for (int nt = 0; nt < 8; nt++) {
        const int col = nt*8 + 2*tig;
        *(float2*)&g_opart[(r0*NCH + c)*HH + col] = make_float2(O[nt][0], O[nt][1]);
        *(float2*)&g_opart[(r1*NCH + c)*HH + col] = make_float2(O[nt][2], O[nt][3]);
    }
    if (tig == 0) {
        g_ml[(r0*NCH + c)*2 + 0] = m0;
        g_ml[(r0*NCH + c)*2 + 1] = l0;
        g_ml[(r1*NCH + c)*2 + 0] = m1;
        g_ml[(r1*NCH + c)*2 + 1] = l1;
    }
}

// ==========================================================================
// Kernel 3: combine. Fixed fully-unrolled 8-chunk loop (zero-init chunks
// contribute nothing; max over extra zeros only shifts normalization).
// ==========================================================================
__global__ __launch_bounds__(64) void attn_combine(float* __restrict__ out)
{
    const size_t r = blockIdx.x;
    const int    e = threadIdx.x;

    float mc[NCH], lc[NCH], op[NCH];
    #pragma unroll
    for (int c = 0; c < NCH; c++) {
        float2 ml = *(const float2*)&g_ml[(r*NCH + c)*2];
        mc[c] = ml.x; lc[c] = ml.y;
        op[c] = g_opart[(r*NCH + c)*HH + e];
    }
    float M = mc[0];
    #pragma unroll
    for (int c = 1; c < NCH; c++) M = fmaxf(M, mc[c]);

    float L = 0.0f, o = 0.0f;
    #pragma unroll
    for (int c = 0; c < NCH; c++) {
        float w = __expf(mc[c] - M);
        L += lc[c] * w;
        o  = fmaf(w, op[c], o);
    }
    out[r*HH + e] = o / L;
}

// ==========================================================================
extern "C" void kernel_launch(void* const* d_in, const int* in_sizes, int n_in,
                              void* d_out, int out_size)
{
    const float* x  = (const float*)d_in[0];
    const float* Wq = (const float*)d_in[1];
    const float* bq = (const float*)d_in[2];
    const float* Wk = (const float*)d_in[3];
    const float* bk = (const float*)d_in[4];
    const float* Wv = (const float*)d_in[5];
    const float* bv = (const float*)d_in[6];
    float* out = (float*)d_out;

    cudaFuncSetAttribute(attn_partial,
                         cudaFuncAttributeMaxDynamicSharedMemorySize, ATTN_SMEM);

    dim3 gw(32, 3);
    wperm<<<gw, 256>>>(Wq, Wk, Wv);

    dim3 gq(NROWS / 128, 3);
    qkv_proj<<<gq, 128>>>(x, bq, bk, bv);

    dim3 ga(SS / 64, NCH, BB);
    attn_partial<<<ga, 128, ATTN_SMEM>>>();

    attn_combine<<<NROWS, 64>>>(out);
}

// round 16
// speedup vs baseline: 1.2141x; 1.0979x over previous
#include <cuda_runtime.h>
#include <math_constants.h>
#include <cstdint>
#include <cstddef>

// Problem shape (fixed by reference)
#define BB  4
#define SS  2048
#define EE  1024
#define HH  64
#define NROWS (BB*SS)     // 8192 query rows
#define CH  256           // keys per split-K chunk (four 64-key subtiles)
#define NCH (SS/CH)       // 8 chunks per batch

// -------- device scratch (no allocations allowed; zero-initialized) --------
__device__ float g_q[NROWS*HH];                  // tf32, e-permuted, pre-scaled
__device__ float g_k[NROWS*HH];                  // tf32, e-permuted
__device__ float g_vt[HH*NROWS];                 // tf32, transposed, tile-permuted
__device__ float g_wp[3*EE*HH];                  // pre-permuted tf32 W (768KB)
__device__ float g_opart[(size_t)NROWS*NCH*HH];  // zero-init matters (combine)
__device__ float g_ml[(size_t)NROWS*NCH*2];      // zero-init matters

// -------- tf32 helpers --------
__device__ __forceinline__ float tf32r(float x) {
    uint32_t u;
    asm("cvt.rna.tf32.f32 %0, %1;" : "=r"(u) : "f"(x));
    return __uint_as_float(u);
}
__device__ __forceinline__ void mma_tf32(float* d, const uint32_t* a, const uint32_t* b) {
    asm volatile(
        "mma.sync.aligned.m16n8k8.row.col.f32.tf32.tf32.f32 "
        "{%0,%1,%2,%3}, {%4,%5,%6,%7}, {%8,%9}, {%0,%1,%2,%3};"
        : "+f"(d[0]), "+f"(d[1]), "+f"(d[2]), "+f"(d[3])
        : "r"(a[0]), "r"(a[1]), "r"(a[2]), "r"(a[3]), "r"(b[0]), "r"(b[1]));
}
__device__ __forceinline__ int perm64(int c) {       // c in 0..63
    return (c & 32) + ((c & 3) << 3) + ((c >> 2) & 7);
}

// ==========================================================================
// Kernel 0: permute W (tf32) into g_wp[mat][k][pn], pn = (n&7)*8 + (n>>3).
// ==========================================================================
__global__ __launch_bounds__(256) void wperm(
    const float* __restrict__ Wq, const float* __restrict__ Wk,
    const float* __restrict__ Wv)
{
    const int mat = blockIdx.y;
    const float* W = (mat == 0) ? Wq : (mat == 1) ? Wk : Wv;
    float* dst = g_wp + mat * (EE*HH);
    #pragma unroll
    for (int i = 0; i < 8; i++) {
        int idx = blockIdx.x * 2048 + i*256 + threadIdx.x;
        int k = idx >> 6, n = idx & 63;
        dst[k*64 + ((n & 7) << 3) + (n >> 3)] = tf32r(W[idx]);
    }
}

// ==========================================================================
// Kernel 1: QKV projection. CHANGE vs round 12: tile M 128 -> 64, block
// 64 thr (2 warps, each still owning 2 m-tiles -> B-frag reuse preserved).
// Grid (128, 3) = 384 blocks = 2.6 waves (was 192 = 1.3 waves; wave-2 was
// 70% idle). Per-warp instruction mix identical to the round-12 winner.
// ==========================================================================
#define QK_XST 36
#define QK_WST 68

__global__ __launch_bounds__(64) void qkv_proj(
    const float* __restrict__ x,
    const float* __restrict__ bq, const float* __restrict__ bk,
    const float* __restrict__ bv)
{
    __shared__ float xs[64*QK_XST];       // natural [row][k], 9.2 KB
    __shared__ float ws[32*QK_WST];       // permuted [k][pn], 8.7 KB

    const int tid  = threadIdx.x;
    const int warp = tid >> 5;
    const int lane = tid & 31;
    const int g    = lane >> 2;
    const int tig  = lane & 3;
    const int row0 = blockIdx.x * 64;
    const int mat  = blockIdx.y;

    const float* wp   = g_wp + mat * (EE*HH);
    const float* bias = (mat == 0) ? bq : (mat == 1) ? bk : bv;

    // prefetch first tiles: x 64x32 = 512 f4 (8/thread), W 32x64 = 512 f4 (8/thread)
    float4 xt[8], wt[8];
    #pragma unroll
    for (int i = 0; i < 8; i++) {
        int f4 = i*64 + tid;
        xt[i] = *(const float4*)&x[(size_t)(row0 + (f4>>3))*EE + (f4&7)*4];
        wt[i] = *(const float4*)&wp[(size_t)(f4>>4)*64 + (f4&15)*4];
    }

    float acc[2][8][4] = {};

    #pragma unroll 1
    for (int kb = 0; kb < EE; kb += 32) {
        // ---- stage: x natural (tf32), W pure copy ----
        #pragma unroll
        for (int i = 0; i < 8; i++) {
            int f4 = i*64 + tid;
            int r = f4 >> 3, c4 = f4 & 7;
            float4 t;
            t.x = tf32r(xt[i].x); t.y = tf32r(xt[i].y);
            t.z = tf32r(xt[i].z); t.w = tf32r(xt[i].w);
            *(float4*)&xs[r*QK_XST + c4*4] = t;
            *(float4*)&ws[(f4>>4)*QK_WST + (f4&15)*4] = wt[i];
        }
        __syncthreads();

        if (kb + 32 < EE) {
            #pragma unroll
            for (int i = 0; i < 8; i++) {
                int f4 = i*64 + tid;
                xt[i] = *(const float4*)&x[(size_t)(row0 + (f4>>3))*EE + kb+32 + (f4&7)*4];
                wt[i] = *(const float4*)&wp[(size_t)(kb+32 + (f4>>4))*64 + (f4&15)*4];
            }
        }

        // ---- compute: warp rows warp*32..+31 (2 m-tiles), B reused ----
        #pragma unroll
        for (int ks = 0; ks < 4; ks++) {
            float w1[8], w2[8];
            *(float4*)&w1[0] = *(const float4*)&ws[(8*ks+tig  )*QK_WST + g*8    ];
            *(float4*)&w1[4] = *(const float4*)&ws[(8*ks+tig  )*QK_WST + g*8 + 4];
            *(float4*)&w2[0] = *(const float4*)&ws[(8*ks+tig+4)*QK_WST + g*8    ];
            *(float4*)&w2[4] = *(const float4*)&ws[(8*ks+tig+4)*QK_WST + g*8 + 4];
            #pragma unroll
            for (int mt = 0; mt < 2; mt++) {
                const int rb = warp*32 + mt*16 + g;
                uint32_t a[4];
                a[0] = __float_as_uint(xs[ rb   *QK_XST + 8*ks + tig    ]);
                a[1] = __float_as_uint(xs[(rb+8)*QK_XST + 8*ks + tig    ]);
                a[2] = __float_as_uint(xs[ rb   *QK_XST + 8*ks + tig + 4]);
                a[3] = __float_as_uint(xs[(rb+8)*QK_XST + 8*ks + tig + 4]);
                #pragma unroll
                for (int nt = 0; nt < 8; nt++) {
                    uint32_t bf[2] = { __float_as_uint(w1[nt]), __float_as_uint(w2[nt]) };
                    mma_tf32(acc[mt][nt], a, bf);
                }
            }
        }
        __syncthreads();
    }

    // ---- epilogue: write attention-ready layouts ----
    #pragma unroll
    for (int mt = 0; mt < 2; mt++) {
        const int rowa = row0 + warp*32 + mt*16 + g;
        const int rowb = rowa + 8;
        #pragma unroll
        for (int nt = 0; nt < 8; nt++) {
            const int col = nt*8 + 2*tig;
            const float b0 = __ldg(&bias[col]);
            const float b1 = __ldg(&bias[col+1]);
            float v0 = acc[mt][nt][0] + b0, v1 = acc[mt][nt][1] + b1;
            float v2 = acc[mt][nt][2] + b0, v3 = acc[mt][nt][3] + b1;
            if (mat == 0) {            // Q: scale + tf32 + e-permuted
                const int p = perm64(col);
                g_q[(size_t)rowa*HH + p]     = tf32r(v0 * 0.125f);
                g_q[(size_t)rowa*HH + p + 8] = tf32r(v1 * 0.125f);
                g_q[(size_t)rowb*HH + p]     = tf32r(v2 * 0.125f);
                g_q[(size_t)rowb*HH + p + 8] = tf32r(v3 * 0.125f);
            } else if (mat == 1) {     // K: tf32 + e-permuted
                const int p = perm64(col);
                g_k[(size_t)rowa*HH + p]     = tf32r(v0);
                g_k[(size_t)rowa*HH + p + 8] = tf32r(v1);
                g_k[(size_t)rowb*HH + p]     = tf32r(v2);
                g_k[(size_t)rowb*HH + p + 8] = tf32r(v3);
            } else {                   // V: tf32, transposed, key tile-permuted
                const size_t ta = (size_t)(rowa & ~63) + perm64(rowa & 63);
                const size_t tb = (size_t)(rowb & ~63) + perm64(rowb & 63);
                g_vt[(size_t) col   *NROWS + ta] = tf32r(v0);
                g_vt[(size_t)(col+1)*NROWS + ta] = tf32r(v1);
                g_vt[(size_t) col   *NROWS + tb] = tf32r(v2);
                g_vt[(size_t)(col+1)*NROWS + tb] = tf32r(v3);
            }
        }
    }
}

// ==========================================================================
// Kernel 2: split-K causal flash attention (exact round-12 winner).
// ALL staging = pure float4 copy. Block 128 thr; 64 q x 256 keys.
// AST = 68: conflict-free fragment loads. Grid (qt=32, c=8, b=4).
// ==========================================================================
#define AST 68
#define ATTN_SMEM (3*64*AST*4)   // 52.2 KB

__global__ __launch_bounds__(128) void attn_partial()
{
    extern __shared__ float dsm[];
    float* Qs  = dsm;
    float* KPs = dsm + 64*AST;
    float* Vst = dsm + 2*64*AST;

    const int tid  = threadIdx.x;
    const int warp = tid >> 5;
    const int lane = tid & 31;
    const int g    = lane >> 2;
    const int tig  = lane & 3;
    const int qt   = blockIdx.x;
    const int c    = blockIdx.y;
    const int b    = blockIdx.z;
    if (4*c > qt) return;

    const int q0 = qt * 64;
    const int wq = warp * 16;

    // ---- stage Q: pure copy ----
    #pragma unroll
    for (int i = 0; i < 8; i++) {
        int f4 = i*128 + tid;
        int r = f4 >> 4, c4 = f4 & 15;
        *(float4*)&Qs[r*AST + c4*4] =
            *(const float4*)&g_q[((size_t)b*SS + q0 + r)*HH + c4*4];
    }

    float O[8][4] = {};
    float m0 = -CUDART_INF_F, m1 = -CUDART_INF_F;
    float l0 = 0.0f, l1 = 0.0f;

    #pragma unroll 1
    for (int sub = 0; sub < 4; sub++) {
        const int k0 = c*CH + sub*64;
        if (k0 > q0) break;
        const bool diag = (k0 == q0);

        __syncthreads();
        // ---- stage K: pure copy ----
        #pragma unroll
        for (int i = 0; i < 8; i++) {
            int f4 = i*128 + tid;
            int r = f4 >> 4, c4 = f4 & 15;
            *(float4*)&KPs[r*AST + c4*4] =
                *(const float4*)&g_k[((size_t)b*SS + k0 + r)*HH + c4*4];
        }
        // ---- stage V: pure copy from transposed g_vt ----
        #pragma unroll
        for (int i = 0; i < 8; i++) {
            int f4 = i*128 + tid;
            int h = f4 >> 4, j4 = f4 & 15;
            *(float4*)&Vst[h*AST + j4*4] =
                *(const float4*)&g_vt[(size_t)h*NROWS + (size_t)b*SS + k0 + j4*4];
        }
        __syncthreads();

        // ---- Phase A: S = Qhat Khat^T ----
        float S[8][4] = {};
        #pragma unroll
        for (int eb = 0; eb < 2; eb++) {
            float al[8], ah[8];
            *(float4*)&al[0] = *(const float4*)&Qs[(wq+g  )*AST + eb*32 + tig*8    ];
            *(float4*)&al[4] = *(const float4*)&Qs[(wq+g  )*AST + eb*32 + tig*8 + 4];
            *(float4*)&ah[0] = *(const float4*)&Qs[(wq+g+8)*AST + eb*32 + tig*8    ];
            *(float4*)&ah[4] = *(const float4*)&Qs[(wq+g+8)*AST + eb*32 + tig*8 + 4];
            #pragma unroll
            for (int nh = 0; nh < 2; nh++) {
                float kv[4][8];
                #pragma unroll
                for (int j = 0; j < 4; j++) {
                    int nt = nh*4 + j;
                    *(float4*)&kv[j][0] = *(const float4*)&KPs[(nt*8+g)*AST + eb*32 + tig*8    ];
                    *(float4*)&kv[j][4] = *(const float4*)&KPs[(nt*8+g)*AST + eb*32 + tig*8 + 4];
                }
                #pragma unroll
                for (int k2 = 0; k2 < 4; k2++) {
                    uint32_t a[4];
                    a[0] = __float_as_uint(al[2*k2  ]);
                    a[1] = __float_as_uint(ah[2*k2  ]);
                    a[2] = __float_as_uint(al[2*k2+1]);
                    a[3] = __float_as_uint(ah[2*k2+1]);
                    #pragma unroll
                    for (int j = 0; j < 4; j++) {
                        uint32_t bf[2] = { __float_as_uint(kv[j][2*k2]),
                                           __float_as_uint(kv[j][2*k2+1]) };
                        mma_tf32(S[nh*4+j], a, bf);
                    }
                }
            }
        }

        // ---- causal mask (diagonal subtile only) ----
        const int gq0 = q0 + wq + g;
        const int gq1 = gq0 + 8;
        if (diag) {
            #pragma unroll
            for (int nt = 0; nt < 8; nt++) {
                const int kc = k0 + nt*8 + 2*tig;
                if (kc   > gq0) S[nt][0] = -CUDART_INF_F;
                if (kc+1 > gq0) S[nt][1] = -CUDART_INF_F;
                if (kc   > gq1) S[nt][2] = -CUDART_INF_F;
                if (kc+1 > gq1) S[nt][3] = -CUDART_INF_F;
            }
        }

        // ---- online softmax (quad shfl) ----
        float mx0 = -CUDART_INF_F, mx1 = -CUDART_INF_F;
        #pragma unroll
        for (int nt = 0; nt < 8; nt++) {
            mx0 = fmaxf(mx0, fmaxf(S[nt][0], S[nt][1]));
            mx1 = fmaxf(mx1, fmaxf(S[nt][2], S[nt][3]));
        }
        mx0 = fmaxf(mx0, __shfl_xor_sync(0xffffffffu, mx0, 1));
        mx0 = fmaxf(mx0, __shfl_xor_sync(0xffffffffu, mx0, 2));
        mx1 = fmaxf(mx1, __shfl_xor_sync(0xffffffffu, mx1, 1));
        mx1 = fmaxf(mx1, __shfl_xor_sync(0xffffffffu, mx1, 2));

        const float nm0 = fmaxf(m0, mx0), nm1 = fmaxf(m1, mx1);
        const float al0 = __expf(m0 - nm0), al1 = __expf(m1 - nm1);
        m0 = nm0; m1 = nm1;

        float s0 = 0.0f, s1 = 0.0f;
        #pragma unroll
        for (int nt = 0; nt < 8; nt++) {
            S[nt][0] = __expf(S[nt][0] - nm0);
            S[nt][1] = __expf(S[nt][1] - nm0);
            S[nt][2] = __expf(S[nt][2] - nm1);
            S[nt][3] = __expf(S[nt][3] - nm1);
            s0 += S[nt][0] + S[nt][1];
            s1 += S[nt][2] + S[nt][3];
        }
        s0 += __shfl_xor_sync(0xffffffffu, s0, 1);
        s0 += __shfl_xor_sync(0xffffffffu, s0, 2);
        s1 += __shfl_xor_sync(0xffffffffu, s1, 1);
        s1 += __shfl_xor_sync(0xffffffffu, s1, 2);
        l0 = l0*al0 + s0;
        l1 = l1*al1 + s1;
        #pragma unroll
        for (int nt = 0; nt < 8; nt++) {
            O[nt][0] *= al0; O[nt][1] *= al0;
            O[nt][2] *= al1; O[nt][3] *= al1;
        }

        __syncthreads();
        // ---- stage P over K region (tf32, key-permuted) ----
        #pragma unroll
        for (int nt = 0; nt < 8; nt++) {
            const int p0 = perm64(nt*8 + 2*tig);
            KPs[(wq+g  )*AST + p0    ] = tf32r(S[nt][0]);
            KPs[(wq+g  )*AST + p0 + 8] = tf32r(S[nt][1]);
            KPs[(wq+g+8)*AST + p0    ] = tf32r(S[nt][2]);
            KPs[(wq+g+8)*AST + p0 + 8] = tf32r(S[nt][3]);
        }
        __syncthreads();

        // ---- Phase B: O += P V ----
        #pragma unroll
        for (int kb = 0; kb < 2; kb++) {
            float al2[8], ah2[8];
            *(float4*)&al2[0] = *(const float4*)&KPs[(wq+g  )*AST + kb*32 + tig*8    ];
            *(float4*)&al2[4] = *(const float4*)&KPs[(wq+g  )*AST + kb*32 + tig*8 + 4];
            *(float4*)&ah2[0] = *(const float4*)&KPs[(wq+g+8)*AST + kb*32 + tig*8    ];
            *(float4*)&ah2[4] = *(const float4*)&KPs[(wq+g+8)*AST + kb*32 + tig*8 + 4];
            #pragma unroll
            for (int nh = 0; nh < 2; nh++) {
                float vv[4][8];
                #pragma unroll
                for (int j = 0; j < 4; j++) {
                    int nt = nh*4 + j;
                    *(float4*)&vv[j][0] = *(const float4*)&Vst[(nt*8+g)*AST + kb*32 + tig*8    ];
                    *(float4*)&vv[j][4] = *(const float4*)&Vst[(nt*8+g)*AST + kb*32 + tig*8 + 4];
                }
                #pragma unroll
                for (int k2 = 0; k2 < 4; k2++) {
                    uint32_t a[4];
                    a[0] = __float_as_uint(al2[2*k2  ]);
                    a[1] = __float_as_uint(ah2[2*k2  ]);
                    a[2] = __float_as_uint(al2[2*k2+1]);
                    a[3] = __float_as_uint(ah2[2*k2+1]);
                    #pragma unroll
                    for (int j = 0; j < 4; j++) {
                        uint32_t bf[2] = { __float_as_uint(vv[j][2*k2]),
                                           __float_as_uint(vv[j][2*k2+1]) };
                        mma_tf32(O[nh*4+j], a, bf);
                    }
                }
            }
        }
    }

    // ---- write unnormalized partials + (m, l) ----
    const size_t r0 = (size_t)b*SS + q0 + wq + g;
    const size_t r1 = r0 + 8;
    #pragma unroll
    for (int nt = 0; nt < 8; nt++) {
        const int col = nt*8 + 2*tig;
        *(float2*)&g_opart[(r0*NCH + c)*HH + col] = make_float2(O[nt][0], O[nt][1]);
        *(float2*)&g_opart[(r1*NCH + c)*HH + col] = make_float2(O[nt][2], O[nt][3]);
    }
    if (tig == 0) {
        g_ml[(r0*NCH + c)*2 + 0] = m0;
        g_ml[(r0*NCH + c)*2 + 1] = l0;
        g_ml[(r1*NCH + c)*2 + 0] = m1;
        g_ml[(r1*NCH + c)*2 + 1] = l1;
    }
}

// ==========================================================================
// Kernel 3: combine. Fixed fully-unrolled 8-chunk loop (zero-init chunks
// contribute nothing; max over extra zeros only shifts normalization).
// ==========================================================================
__global__ __launch_bounds__(64) void attn_combine(float* __restrict__ out)
{
    const size_t r = blockIdx.x;
    const int    e = threadIdx.x;

    float mc[NCH], lc[NCH], op[NCH];
    #pragma unroll
    for (int c = 0; c < NCH; c++) {
        float2 ml = *(const float2*)&g_ml[(r*NCH + c)*2];
        mc[c] = ml.x; lc[c] = ml.y;
        op[c] = g_opart[(r*NCH + c)*HH + e];
    }
    float M = mc[0];
    #pragma unroll
    for (int c = 1; c < NCH; c++) M = fmaxf(M, mc[c]);

    float L = 0.0f, o = 0.0f;
    #pragma unroll
    for (int c = 0; c < NCH; c++) {
        float w = __expf(mc[c] - M);
        L += lc[c] * w;
        o  = fmaf(w, op[c], o);
    }
    out[r*HH + e] = o / L;
}

// ==========================================================================
extern "C" void kernel_launch(void* const* d_in, const int* in_sizes, int n_in,
                              void* d_out, int out_size)
{
    const float* x  = (const float*)d_in[0];
    const float* Wq = (const float*)d_in[1];
    const float* bq = (const float*)d_in[2];
    const float* Wk = (const float*)d_in[3];
    const float* bk = (const float*)d_in[4];
    const float* Wv = (const float*)d_in[5];
    const float* bv = (const float*)d_in[6];
    float* out = (float*)d_out;

    cudaFuncSetAttribute(attn_partial,
                         cudaFuncAttributeMaxDynamicSharedMemorySize, ATTN_SMEM);

    dim3 gw(32, 3);
    wperm<<<gw, 256>>>(Wq, Wk, Wv);

    dim3 gq(NROWS / 64, 3);
    qkv_proj<<<gq, 64>>>(x, bq, bk, bv);

    dim3 ga(SS / 64, NCH, BB);
    attn_partial<<<ga, 128, ATTN_SMEM>>>();

    attn_combine<<<NROWS, 64>>>(out);
}